// round 3
// baseline (speedup 1.0000x reference)
#include <cuda_runtime.h>
#include <cuda_bf16.h>

#define BB 32
#define TT 2000
#define HH 512
#define LL 256
#define LL1 (LL+1)
#define H4 (HH/4)
#define CH 800            // frames per smem chunk
#define NCH 3             // ceil(2000/800)
#define PAD 33            // bank-conflict-free transposed layout
#define SMEMSZ (2*CH*PAD*4)

// Scratch (device globals — no allocation allowed)
__device__ float g_I[TT*BB];       // integrate state BEFORE frame t, [t*32+b]
__device__ float g_scale[BB];      // per-batch rescale factor
__device__ float g_w[BB*TT];       // per-frame weight, row-major [b][t]
__device__ int   g_fpos[BB*LL1];   // frame index of k-th fire
__device__ float g_carry[BB*LL1];  // carry weight into token k
__device__ int   g_nf[BB];         // emitted tokens (<= LL)

// ---------------- Kernel A: lean serial integrate chain ----------------
// 1 block, 1024 threads. Warp w sums batch w (f64) -> scale. Scaled alphas are
// staged transposed into double-buffered smem chunks; warps 1..31 stage chunk
// c+1 while warp 0 runs the 12-cyc/iter serial chain on chunk c, storing only
// I_t (coalesced STG). All bookkeeping deferred to kernel B.
__global__ void __launch_bounds__(1024) cif_scan_kernel(
    const float* __restrict__ alphas, const int* __restrict__ tlen)
{
    extern __shared__ float sa[];          // [2][CH*PAD], sa[buf][t*PAD + b]
    __shared__ float sscale[BB];

    const int tid = threadIdx.x;
    const int wid = tid >> 5;
    const int lid = tid & 31;

    // 1. per-warp f64 sum -> scale (f32 div as reference)
    {
        const float* arow = alphas + wid * TT;
        double acc = 0.0;
        for (int t = lid; t < TT; t += 32) acc += (double)arow[t];
        #pragma unroll
        for (int o = 16; o; o >>= 1) acc += __shfl_down_sync(0xFFFFFFFFu, acc, o);
        if (lid == 0) {
            float s = (float)tlen[wid] / (float)acc;
            sscale[wid] = s;
            g_scale[wid] = s;
        }
    }
    __syncthreads();

    // 2. stage chunk 0 (all 32 warps, warp w = batch w), scaled + transposed
    {
        const float s = sscale[wid];
        const float* src = alphas + wid * TT;
        for (int t = lid; t < CH; t += 32)
            sa[t * PAD + wid] = __fmul_rn(src[t], s);
    }
    __syncthreads();

    // 3. pipelined serial chain
    float I = 0.0f;
    for (int c = 0; c < NCH; ++c) {
        const int len = (TT - c * CH < CH) ? (TT - c * CH) : CH;
        if (wid > 0 && c + 1 < NCH) {
            // stage next chunk (31 warps cover 32 batches)
            const int base = (c + 1) * CH;
            const int len2 = (TT - base < CH) ? (TT - base) : CH;
            float* dst = sa + ((c + 1) & 1) * (CH * PAD);
            for (int b = wid - 1; b < BB; b += 31) {
                const float s = sscale[b];
                const float* src = alphas + b * TT + base;
                for (int t = lid; t < len2; t += 32)
                    dst[t * PAD + b] = __fmul_rn(src[t], s);
            }
        } else if (wid == 0) {
            const float* buf = sa + (c & 1) * (CH * PAD);
            const int tg = c * CH;
            #pragma unroll 8
            for (int tt = 0; tt < len; ++tt) {
                g_I[(tg + tt) * BB + lid] = I;       // I before this frame
                float a   = buf[tt * PAD + lid];
                float I1  = __fadd_rn(I, a);
                bool fire = (I1 >= 0.95f);
                float I1m = __fadd_rn(I1, -1.0f);
                I = fire ? I1m : I1;
            }
        }
        __syncthreads();
    }
}

// ---------------- Kernel B: parallel bookkeeping ----------------
// Block = batch. Recompute fire/w/remainds bit-exactly from g_I + alphas*scale,
// block prefix-scan fires -> token indices, scatter fpos/carry, write w.
__global__ void __launch_bounds__(1024) cif_book_kernel(
    const float* __restrict__ alphas)
{
    __shared__ int wsum[32];
    __shared__ int stotal;

    const int b    = blockIdx.x;
    const int tid  = threadIdx.x;
    const int lane = tid & 31;
    const int wid  = tid >> 5;
    const float s  = g_scale[b];

    int f0 = 0, f1 = 0;
    float r0 = 0.f, r1 = 0.f;
    const int t0 = tid * 2;

    if (t0 < TT) {
        float a0 = __fmul_rn(alphas[b * TT + t0],     s);
        float a1 = __fmul_rn(alphas[b * TT + t0 + 1], s);
        float I0 = g_I[t0 * BB + b];
        float I1 = g_I[(t0 + 1) * BB + b];
        f0 = (__fadd_rn(I0, a0) >= 0.95f);
        f1 = (__fadd_rn(I1, a1) >= 0.95f);
        float w0 = f0 ? __fadd_rn(1.0f, -I0) : a0;   // cur (reference ops)
        float w1 = f1 ? __fadd_rn(1.0f, -I1) : a1;
        r0 = __fadd_rn(a0, -w0);                      // remainds
        r1 = __fadd_rn(a1, -w1);
        *(float2*)&g_w[b * TT + t0] = make_float2(w0, w1);
    }

    // block exclusive scan over fire counts
    int cnt = f0 + f1, sc = cnt;
    #pragma unroll
    for (int o = 1; o < 32; o <<= 1) {
        int v = __shfl_up_sync(0xFFFFFFFFu, sc, o);
        if (lane >= o) sc += v;
    }
    if (lane == 31) wsum[wid] = sc;
    __syncthreads();
    if (tid < 32) {
        int v = wsum[tid], s2 = v;
        #pragma unroll
        for (int o = 1; o < 32; o <<= 1) {
            int u = __shfl_up_sync(0xFFFFFFFFu, s2, o);
            if (tid >= o) s2 += u;
        }
        wsum[tid] = s2 - v;              // exclusive warp offsets
        if (tid == 31) stotal = s2;
    }
    __syncthreads();

    const int base = wsum[wid] + sc - cnt;   // exclusive prefix for this thread
    if (f0 && base < LL) {
        g_fpos [b * LL1 + base]     = t0;
        g_carry[b * LL1 + base + 1] = r0;
    }
    const int k1 = base + f0;
    if (f1 && k1 < LL) {
        g_fpos [b * LL1 + k1]     = t0 + 1;
        g_carry[b * LL1 + k1 + 1] = r1;
    }
    if (tid == 0) {
        g_carry[b * LL1] = 0.0f;
        g_nf[b] = (stotal < LL) ? stotal : LL;
    }
}

// ---------------- Kernel C: weighted segmented reduction ----------------
__global__ void __launch_bounds__(128) cif_gather_kernel(
    const float* __restrict__ hidden, float* __restrict__ out)
{
    const int k  = blockIdx.x;
    const int b  = blockIdx.y;
    const int h4 = threadIdx.x;

    float4* o = (float4*)out + (size_t)(b * LL + k) * H4 + h4;

    const int nfb = g_nf[b];
    if (k >= nfb) {
        *o = make_float4(0.f, 0.f, 0.f, 0.f);
        return;
    }

    const float4* hid = (const float4*)hidden + (size_t)b * TT * H4 + h4;
    const float*  wrow = g_w + b * TT;

    const int e = g_fpos[b * LL1 + k];
    float4 acc = make_float4(0.f, 0.f, 0.f, 0.f);
    int t0;
    if (k == 0) {
        t0 = 0;
    } else {
        int   sfr = g_fpos[b * LL1 + k - 1];
        float cw  = g_carry[b * LL1 + k];
        float4 hv = hid[(size_t)sfr * H4];
        acc.x = cw * hv.x; acc.y = cw * hv.y;
        acc.z = cw * hv.z; acc.w = cw * hv.w;
        t0 = sfr + 1;
    }

    #pragma unroll 8
    for (int t = t0; t <= e; ++t) {
        float  w  = __ldg(wrow + t);
        float4 hv = hid[(size_t)t * H4];
        acc.x = fmaf(w, hv.x, acc.x);
        acc.y = fmaf(w, hv.y, acc.y);
        acc.z = fmaf(w, hv.z, acc.z);
        acc.w = fmaf(w, hv.w, acc.w);
    }
    *o = acc;
}

extern "C" void kernel_launch(void* const* d_in, const int* in_sizes, int n_in,
                              void* d_out, int out_size)
{
    const float* hidden = (const float*)d_in[0];   // [32,2000,512] f32
    const float* alphas = (const float*)d_in[1];   // [32,2000]     f32
    const int*   tlen   = (const int*)d_in[2];     // [32]          i32
    float*       out    = (float*)d_out;           // [32,256,512]  f32

    cudaFuncSetAttribute(cif_scan_kernel,
                         cudaFuncAttributeMaxDynamicSharedMemorySize, SMEMSZ);
    cif_scan_kernel<<<1, 1024, SMEMSZ>>>(alphas, tlen);
    cif_book_kernel<<<BB, 1024>>>(alphas);
    dim3 grid(LL, BB);
    cif_gather_kernel<<<grid, 128>>>(hidden, out);
}

// round 5
// speedup vs baseline: 1.0181x; 1.0181x over previous
#include <cuda_runtime.h>
#include <cuda_bf16.h>

#define BB 32
#define TT 2000
#define HH 512
#define LL 256
#define LL1 (LL+1)
#define H4 (HH/4)
#define CH 800            // frames per smem chunk (divisible by 8)
#define NCH 3             // ceil(2000/800): 800,800,400
#define PAD 33            // conflict-free transposed staging
#define SMEMSZ (2*CH*PAD*4)

// Scratch (device globals — no allocation allowed)
__device__ float g_I[BB*TT];       // integrate state BEFORE frame t, ROW-major [b][t]
__device__ float g_scale[BB];      // per-batch rescale factor
__device__ float g_w[BB*TT];       // per-frame weight, row-major [b][t]
__device__ int   g_fpos[BB*LL1];   // frame index of k-th fire
__device__ float g_carry[BB*LL1];  // carry weight into token k
__device__ int   g_nf[BB];         // emitted tokens (<= LL)

// ---------------- Kernel A: lean serial integrate chain ----------------
// 1 block, 1024 threads. Warp w: f64-sum batch w -> scale. Warps 1..31 stage
// scaled alphas (transposed) for chunk c+1 while warp 0 (lane=batch) runs the
// serial chain on chunk c with a register ring buffer: LDS and STG fully off
// the 12-cyc FADD/FSETP/FSEL critical chain.
__global__ void __launch_bounds__(1024) cif_scan_kernel(
    const float* __restrict__ alphas, const int* __restrict__ tlen)
{
    extern __shared__ float sa[];          // [2][CH*PAD], sa[buf][t*PAD + b]
    __shared__ float sscale[BB];

    const int tid = threadIdx.x;
    const int wid = tid >> 5;
    const int lid = tid & 31;

    // 1. per-warp f64 sum -> scale (f32 div as reference)
    {
        const float* arow = alphas + wid * TT;
        double acc = 0.0;
        for (int t = lid; t < TT; t += 32) acc += (double)arow[t];
        #pragma unroll
        for (int o = 16; o; o >>= 1) acc += __shfl_down_sync(0xFFFFFFFFu, acc, o);
        if (lid == 0) {
            float s = (float)tlen[wid] / (float)acc;
            sscale[wid] = s;
            g_scale[wid] = s;
        }
    }
    __syncthreads();

    // 2. stage chunk 0 (warp w = batch w), scaled + transposed
    {
        const float s = sscale[wid];
        const float* src = alphas + wid * TT;
        for (int t = lid; t < CH; t += 32)
            sa[t * PAD + wid] = __fmul_rn(src[t], s);
    }
    __syncthreads();

    // 3. pipelined serial chain
    float I = 0.0f;
    for (int c = 0; c < NCH; ++c) {
        const int len = (TT - c * CH < CH) ? (TT - c * CH) : CH;
        if (wid > 0) {
            if (c + 1 < NCH) {          // stage next chunk (31 warps, 32 batches)
                const int base = (c + 1) * CH;
                const int len2 = (TT - base < CH) ? (TT - base) : CH;
                float* dst = sa + ((c + 1) & 1) * (CH * PAD);
                for (int b = wid - 1; b < BB; b += 31) {
                    const float s = sscale[b];
                    const float* src = alphas + b * TT + base;
                    for (int t = lid; t < len2; t += 32)
                        dst[t * PAD + b] = __fmul_rn(src[t], s);
                }
            }
        } else {
            const float* buf = sa + (c & 1) * (CH * PAD);
            const int tg = c * CH;
            float ab[8], an[8], Ib[8];
            #pragma unroll
            for (int j = 0; j < 8; ++j) ab[j] = buf[j * PAD + lid];

            for (int tt = 0; tt < len; tt += 8) {
                const bool pf = (tt + 8 < len);
                #pragma unroll
                for (int j = 0; j < 8; ++j)          // prefetch next group
                    an[j] = pf ? buf[(tt + 8 + j) * PAD + lid] : 0.0f;

                #pragma unroll
                for (int j = 0; j < 8; ++j) {        // 12-cyc/iter chain
                    Ib[j]     = I;
                    float I1  = __fadd_rn(I, ab[j]);
                    float I1m = __fadd_rn(I1, -1.0f);
                    I = (I1 >= 0.95f) ? I1m : I1;    // want FSEL (pred-as-data)
                }

                float* Ip = g_I + lid * TT + tg + tt;
                *(float4*)(Ip)     = make_float4(Ib[0], Ib[1], Ib[2], Ib[3]);
                *(float4*)(Ip + 4) = make_float4(Ib[4], Ib[5], Ib[6], Ib[7]);

                #pragma unroll
                for (int j = 0; j < 8; ++j) ab[j] = an[j];
            }
        }
        __syncthreads();
    }
}

// ---------------- Kernel B: parallel bookkeeping ----------------
// Block = batch. Recompute fire/w/remainds bit-exactly from g_I + alphas*scale,
// block prefix-scan fires -> token indices, scatter fpos/carry, write w.
__global__ void __launch_bounds__(1024) cif_book_kernel(
    const float* __restrict__ alphas)
{
    __shared__ int wsum[32];
    __shared__ int stotal;

    const int b    = blockIdx.x;
    const int tid  = threadIdx.x;
    const int lane = tid & 31;
    const int wid  = tid >> 5;
    const float s  = g_scale[b];

    int f0 = 0, f1 = 0;
    float r0 = 0.f, r1 = 0.f;
    const int t0 = tid * 2;

    if (t0 < TT) {
        float a0 = __fmul_rn(alphas[b * TT + t0],     s);
        float a1 = __fmul_rn(alphas[b * TT + t0 + 1], s);
        float2 Iv = *(const float2*)&g_I[b * TT + t0];
        f0 = (__fadd_rn(Iv.x, a0) >= 0.95f);
        f1 = (__fadd_rn(Iv.y, a1) >= 0.95f);
        float w0 = f0 ? __fadd_rn(1.0f, -Iv.x) : a0;  // cur (reference ops)
        float w1 = f1 ? __fadd_rn(1.0f, -Iv.y) : a1;
        r0 = __fadd_rn(a0, -w0);                       // remainds
        r1 = __fadd_rn(a1, -w1);
        *(float2*)&g_w[b * TT + t0] = make_float2(w0, w1);
    }

    // block exclusive scan over fire counts
    int cnt = f0 + f1, sc = cnt;
    #pragma unroll
    for (int o = 1; o < 32; o <<= 1) {
        int v = __shfl_up_sync(0xFFFFFFFFu, sc, o);
        if (lane >= o) sc += v;
    }
    if (lane == 31) wsum[wid] = sc;
    __syncthreads();
    if (tid < 32) {
        int v = wsum[tid], s2 = v;
        #pragma unroll
        for (int o = 1; o < 32; o <<= 1) {
            int u = __shfl_up_sync(0xFFFFFFFFu, s2, o);
            if (tid >= o) s2 += u;
        }
        wsum[tid] = s2 - v;              // exclusive warp offsets
        if (tid == 31) stotal = s2;
    }
    __syncthreads();

    const int base = wsum[wid] + sc - cnt;
    if (f0 && base < LL) {
        g_fpos [b * LL1 + base]     = t0;
        g_carry[b * LL1 + base + 1] = r0;
    }
    const int k1 = base + f0;
    if (f1 && k1 < LL) {
        g_fpos [b * LL1 + k1]     = t0 + 1;
        g_carry[b * LL1 + k1 + 1] = r1;
    }
    if (tid == 0) {
        g_carry[b * LL1] = 0.0f;
        g_nf[b] = (stotal < LL) ? stotal : LL;
    }
}

// ---------------- Kernel C: weighted segmented reduction ----------------
__global__ void __launch_bounds__(128) cif_gather_kernel(
    const float* __restrict__ hidden, float* __restrict__ out)
{
    const int k  = blockIdx.x;
    const int b  = blockIdx.y;
    const int h4 = threadIdx.x;

    float4* o = (float4*)out + (size_t)(b * LL + k) * H4 + h4;

    const int nfb = g_nf[b];
    if (k >= nfb) {
        *o = make_float4(0.f, 0.f, 0.f, 0.f);
        return;
    }

    const float4* hid = (const float4*)hidden + (size_t)b * TT * H4 + h4;
    const float*  wrow = g_w + b * TT;

    const int e = g_fpos[b * LL1 + k];
    float4 acc = make_float4(0.f, 0.f, 0.f, 0.f);
    int t0;
    if (k == 0) {
        t0 = 0;
    } else {
        int   sfr = g_fpos[b * LL1 + k - 1];
        float cw  = g_carry[b * LL1 + k];
        float4 hv = hid[(size_t)sfr * H4];
        acc.x = cw * hv.x; acc.y = cw * hv.y;
        acc.z = cw * hv.z; acc.w = cw * hv.w;
        t0 = sfr + 1;
    }

    #pragma unroll 8
    for (int t = t0; t <= e; ++t) {
        float  w  = __ldg(wrow + t);
        float4 hv = hid[(size_t)t * H4];
        acc.x = fmaf(w, hv.x, acc.x);
        acc.y = fmaf(w, hv.y, acc.y);
        acc.z = fmaf(w, hv.z, acc.z);
        acc.w = fmaf(w, hv.w, acc.w);
    }
    *o = acc;
}

extern "C" void kernel_launch(void* const* d_in, const int* in_sizes, int n_in,
                              void* d_out, int out_size)
{
    const float* hidden = (const float*)d_in[0];   // [32,2000,512] f32
    const float* alphas = (const float*)d_in[1];   // [32,2000]     f32
    const int*   tlen   = (const int*)d_in[2];     // [32]          i32
    float*       out    = (float*)d_out;           // [32,256,512]  f32

    cudaFuncSetAttribute(cif_scan_kernel,
                         cudaFuncAttributeMaxDynamicSharedMemorySize, SMEMSZ);
    cif_scan_kernel<<<1, 1024, SMEMSZ>>>(alphas, tlen);
    cif_book_kernel<<<BB, 1024>>>(alphas);
    dim3 grid(LL, BB);
    cif_gather_kernel<<<grid, 128>>>(hidden, out);
}

// round 12
// speedup vs baseline: 1.0869x; 1.0676x over previous
#include <cuda_runtime.h>
#include <cuda_bf16.h>
#include <cstdint>

#define BB 32
#define TT 2000
#define HH 512
#define LL 256
#define LL1 (LL+1)
#define H4 (HH/4)
#define CH 800            // frames per smem chunk (divisible by 8)
#define NCH 3             // 800 + 800 + 400
#define PAD 33            // conflict-free transposed staging
#define SMEMSZ (2*CH*PAD*4)

// Scratch (device globals — no allocation allowed)
__device__ float g_I[BB*TT];       // integrate state BEFORE frame t, row-major [b][t]
__device__ float g_scale[BB];      // per-batch rescale factor
__device__ float g_w[BB*TT];       // per-frame weight, row-major [b][t]
__device__ int   g_fpos[BB*LL1];   // frame index of k-th fire
__device__ float g_carry[BB*LL1];  // carry weight into token k
__device__ int   g_nf[BB];         // emitted tokens (<= LL)

// Forced 12-cyc recurrence step: I = (I+a >= 0.95) ? (I+a-1) : (I+a)
#define CIF_STEP(I, a)                                        \
    asm volatile("{\n\t"                                      \
        ".reg .pred p;\n\t"                                   \
        ".reg .f32 t1, t2;\n\t"                               \
        "add.f32 t1, %0, %1;\n\t"                             \
        "setp.ge.f32 p, t1, 0f3F733333;\n\t"                  \
        "add.f32 t2, t1, 0fBF800000;\n\t"                     \
        "selp.f32 %0, t2, t1, p;\n\t"                         \
        "}" : "+f"(I) : "f"(a))

#define LDS_F32(dst, addr)                                    \
    asm volatile("ld.shared.f32 %0, [%1];" : "=f"(dst) : "r"(addr))

// ---------------- Kernel A: lean serial integrate chain ----------------
// 1 block, 512 threads. 16 warps: f64-sum (2 batches/warp) -> scales; stage
// scaled alphas transposed into double-buffered smem chunks (15 warps stage
// chunk c+1 while warp 0, lane = batch, runs the forced-SASS serial chain).
__global__ void __launch_bounds__(512, 1) cif_scan_kernel(
    const float* __restrict__ alphas, const int* __restrict__ tlen)
{
    extern __shared__ float sa[];          // [2][CH*PAD], sa[buf][t*PAD + b]
    __shared__ float sscale[BB];

    const int tid = threadIdx.x;
    const int wid = tid >> 5;
    const int lid = tid & 31;

    // 1. per-warp f64 sums -> scale (f32 div as reference); 2 batches per warp
    for (int b = wid; b < BB; b += 16) {
        const float* arow = alphas + b * TT;
        double acc = 0.0;
        for (int t = lid; t < TT; t += 32) acc += (double)arow[t];
        #pragma unroll
        for (int o = 16; o; o >>= 1) acc += __shfl_down_sync(0xFFFFFFFFu, acc, o);
        if (lid == 0) {
            float s = (float)tlen[b] / (float)acc;
            sscale[b] = s;
            g_scale[b] = s;
        }
    }
    __syncthreads();

    // 2. stage chunk 0 (16 warps, 2 batches each), scaled + transposed
    for (int b = wid; b < BB; b += 16) {
        const float s = sscale[b];
        const float* src = alphas + b * TT;
        for (int t = lid; t < CH; t += 32)
            sa[t * PAD + b] = __fmul_rn(src[t], s);
    }
    __syncthreads();

    // 3. pipelined serial chain (warp 0) + next-chunk staging (warps 1..15)
    float I = 0.0f;
    for (int c = 0; c < NCH; ++c) {
        const int len = (TT - c * CH < CH) ? (TT - c * CH) : CH;
        if (wid > 0) {
            if (c + 1 < NCH) {
                const int base = (c + 1) * CH;
                const int len2 = (TT - base < CH) ? (TT - base) : CH;
                float* dst = sa + ((c + 1) & 1) * (CH * PAD);
                for (int b = wid - 1; b < BB; b += 15) {
                    const float s = sscale[b];
                    const float* src = alphas + b * TT + base;
                    for (int t = lid; t < len2; t += 32)
                        dst[t * PAD + b] = __fmul_rn(src[t], s);
                }
            }
        } else {
            const float* buf = sa + (c & 1) * (CH * PAD);
            const unsigned int sbase =
                (unsigned int)__cvta_generic_to_shared(buf) + lid * 4u;
            const int tg = c * CH;
            float ab[8], an[8], Ib[8];
            #pragma unroll
            for (int j = 0; j < 8; ++j) LDS_F32(ab[j], sbase + j * (PAD * 4));

            for (int tt = 0; tt < len; tt += 8) {
                // prefetch next group (pinned LDS, off-chain); harmless re-read
                // of current group on the final iteration (len % 8 == 0)
                const int tpre = (tt + 8 < len) ? tt + 8 : tt;
                const unsigned int pa = sbase + tpre * (PAD * 4);
                #pragma unroll
                for (int j = 0; j < 8; ++j) LDS_F32(an[j], pa + j * (PAD * 4));

                #pragma unroll
                for (int j = 0; j < 8; ++j) {        // forced 12-cyc chain
                    Ib[j] = I;
                    CIF_STEP(I, ab[j]);
                }

                float* Ip = g_I + lid * TT + tg + tt;
                *(float4*)(Ip)     = make_float4(Ib[0], Ib[1], Ib[2], Ib[3]);
                *(float4*)(Ip + 4) = make_float4(Ib[4], Ib[5], Ib[6], Ib[7]);

                #pragma unroll
                for (int j = 0; j < 8; ++j) ab[j] = an[j];
            }
        }
        __syncthreads();
    }
}

// ---------------- Kernel B: parallel bookkeeping ----------------
// Block = batch. Recompute fire/w/remainds bit-exactly from g_I + alphas*scale,
// block prefix-scan fires -> token indices, scatter fpos/carry, write w.
__global__ void __launch_bounds__(1024) cif_book_kernel(
    const float* __restrict__ alphas)
{
    __shared__ int wsum[32];
    __shared__ int stotal;

    const int b    = blockIdx.x;
    const int tid  = threadIdx.x;
    const int lane = tid & 31;
    const int wid  = tid >> 5;
    const float s  = g_scale[b];

    int f0 = 0, f1 = 0;
    float r0 = 0.f, r1 = 0.f;
    const int t0 = tid * 2;

    if (t0 < TT) {
        float a0 = __fmul_rn(alphas[b * TT + t0],     s);
        float a1 = __fmul_rn(alphas[b * TT + t0 + 1], s);
        float2 Iv = *(const float2*)&g_I[b * TT + t0];
        f0 = (__fadd_rn(Iv.x, a0) >= 0.95f);
        f1 = (__fadd_rn(Iv.y, a1) >= 0.95f);
        float w0 = f0 ? __fadd_rn(1.0f, -Iv.x) : a0;  // cur (reference ops)
        float w1 = f1 ? __fadd_rn(1.0f, -Iv.y) : a1;
        r0 = __fadd_rn(a0, -w0);                       // remainds
        r1 = __fadd_rn(a1, -w1);
        *(float2*)&g_w[b * TT + t0] = make_float2(w0, w1);
    }

    // block exclusive scan over fire counts
    int cnt = f0 + f1, sc = cnt;
    #pragma unroll
    for (int o = 1; o < 32; o <<= 1) {
        int v = __shfl_up_sync(0xFFFFFFFFu, sc, o);
        if (lane >= o) sc += v;
    }
    if (lane == 31) wsum[wid] = sc;
    __syncthreads();
    if (tid < 32) {
        int v = wsum[tid], s2 = v;
        #pragma unroll
        for (int o = 1; o < 32; o <<= 1) {
            int u = __shfl_up_sync(0xFFFFFFFFu, s2, o);
            if (tid >= o) s2 += u;
        }
        wsum[tid] = s2 - v;              // exclusive warp offsets
        if (tid == 31) stotal = s2;
    }
    __syncthreads();

    const int base = wsum[wid] + sc - cnt;
    if (f0 && base < LL) {
        g_fpos [b * LL1 + base]     = t0;
        g_carry[b * LL1 + base + 1] = r0;
    }
    const int k1 = base + f0;
    if (f1 && k1 < LL) {
        g_fpos [b * LL1 + k1]     = t0 + 1;
        g_carry[b * LL1 + k1 + 1] = r1;
    }
    if (tid == 0) {
        g_carry[b * LL1] = 0.0f;
        g_nf[b] = (stotal < LL) ? stotal : LL;
    }
}

// ---------------- Kernel C: weighted segmented reduction ----------------
__global__ void __launch_bounds__(128) cif_gather_kernel(
    const float* __restrict__ hidden, float* __restrict__ out)
{
    const int k  = blockIdx.x;
    const int b  = blockIdx.y;
    const int h4 = threadIdx.x;

    float4* o = (float4*)out + (size_t)(b * LL + k) * H4 + h4;

    const int nfb = g_nf[b];
    if (k >= nfb) {
        *o = make_float4(0.f, 0.f, 0.f, 0.f);
        return;
    }

    const float4* hid = (const float4*)hidden + (size_t)b * TT * H4 + h4;
    const float*  wrow = g_w + b * TT;

    const int e = g_fpos[b * LL1 + k];
    float4 acc = make_float4(0.f, 0.f, 0.f, 0.f);
    int t0;
    if (k == 0) {
        t0 = 0;
    } else {
        int   sfr = g_fpos[b * LL1 + k - 1];
        float cw  = g_carry[b * LL1 + k];
        float4 hv = hid[(size_t)sfr * H4];
        acc.x = cw * hv.x; acc.y = cw * hv.y;
        acc.z = cw * hv.z; acc.w = cw * hv.w;
        t0 = sfr + 1;
    }

    #pragma unroll 8
    for (int t = t0; t <= e; ++t) {
        float  w  = __ldg(wrow + t);
        float4 hv = hid[(size_t)t * H4];
        acc.x = fmaf(w, hv.x, acc.x);
        acc.y = fmaf(w, hv.y, acc.y);
        acc.z = fmaf(w, hv.z, acc.z);
        acc.w = fmaf(w, hv.w, acc.w);
    }
    *o = acc;
}

extern "C" void kernel_launch(void* const* d_in, const int* in_sizes, int n_in,
                              void* d_out, int out_size)
{
    const float* hidden = (const float*)d_in[0];   // [32,2000,512] f32
    const float* alphas = (const float*)d_in[1];   // [32,2000]     f32
    const int*   tlen   = (const int*)d_in[2];     // [32]          i32
    float*       out    = (float*)d_out;           // [32,256,512]  f32

    cudaFuncSetAttribute(cif_scan_kernel,
                         cudaFuncAttributeMaxDynamicSharedMemorySize, SMEMSZ);
    cif_scan_kernel<<<1, 512, SMEMSZ>>>(alphas, tlen);
    cif_book_kernel<<<BB, 1024>>>(alphas);
    dim3 grid(LL, BB);
    cif_gather_kernel<<<grid, 128>>>(hidden, out);
}

// round 16
// speedup vs baseline: 1.1066x; 1.0181x over previous
#include <cuda_runtime.h>
#include <cuda_bf16.h>
#include <cstdint>

#define BB 32
#define TT 2000
#define HH 512
#define LL 256
#define LL1 (LL+1)
#define H4 (HH/4)
#define CH 800            // frames per smem chunk (divisible by 8)
#define NCH 3             // 800 + 800 + 400
#define PAD 33            // conflict-free transposed staging
#define SMEMSZ (2*CH*PAD*4)

// Scratch (device globals — no allocation allowed)
__device__ float g_I[BB*TT];       // integrate state BEFORE frame t, row-major [b][t]
__device__ float g_scale[BB];      // per-batch rescale factor
__device__ float g_w[BB*TT];       // per-frame weight, row-major [b][t]
__device__ int   g_fpos[BB*LL1];   // frame index of k-th fire
__device__ float g_carry[BB*LL1];  // carry weight into token k
__device__ int   g_nf[BB];         // emitted tokens (<= LL)

// 8 fused recurrence steps in ONE asm block (non-volatile: has live outputs).
// Per step: Ib=I; t=I+a; f=(t>=0.95)?1.0:0.0 (FSET, no predicates); I=t-f.
// Bit-exact vs reference: f==1.0 iff fire; t-1.0 exact (Sterbenz).
#define CIF_STEP8(I, a, Ib)                                   \
    asm("{\n\t"                                               \
        ".reg .f32 t, f;\n\t"                                 \
        "mov.f32 %0, %8;\n\t"                                 \
        "add.f32 t, %8, %9;\n\t"                              \
        "set.ge.f32.f32 f, t, 0f3F733333;\n\t"                \
        "sub.f32 %8, t, f;\n\t"                               \
        "mov.f32 %1, %8;\n\t"                                 \
        "add.f32 t, %8, %10;\n\t"                             \
        "set.ge.f32.f32 f, t, 0f3F733333;\n\t"                \
        "sub.f32 %8, t, f;\n\t"                               \
        "mov.f32 %2, %8;\n\t"                                 \
        "add.f32 t, %8, %11;\n\t"                             \
        "set.ge.f32.f32 f, t, 0f3F733333;\n\t"                \
        "sub.f32 %8, t, f;\n\t"                               \
        "mov.f32 %3, %8;\n\t"                                 \
        "add.f32 t, %8, %12;\n\t"                             \
        "set.ge.f32.f32 f, t, 0f3F733333;\n\t"                \
        "sub.f32 %8, t, f;\n\t"                               \
        "mov.f32 %4, %8;\n\t"                                 \
        "add.f32 t, %8, %13;\n\t"                             \
        "set.ge.f32.f32 f, t, 0f3F733333;\n\t"                \
        "sub.f32 %8, t, f;\n\t"                               \
        "mov.f32 %5, %8;\n\t"                                 \
        "add.f32 t, %8, %14;\n\t"                             \
        "set.ge.f32.f32 f, t, 0f3F733333;\n\t"                \
        "sub.f32 %8, t, f;\n\t"                               \
        "mov.f32 %6, %8;\n\t"                                 \
        "add.f32 t, %8, %15;\n\t"                             \
        "set.ge.f32.f32 f, t, 0f3F733333;\n\t"                \
        "sub.f32 %8, t, f;\n\t"                               \
        "mov.f32 %7, %8;\n\t"                                 \
        "add.f32 t, %8, %16;\n\t"                             \
        "set.ge.f32.f32 f, t, 0f3F733333;\n\t"                \
        "sub.f32 %8, t, f;\n\t"                               \
        "}"                                                   \
        : "=f"(Ib[0]), "=f"(Ib[1]), "=f"(Ib[2]), "=f"(Ib[3]), \
          "=f"(Ib[4]), "=f"(Ib[5]), "=f"(Ib[6]), "=f"(Ib[7]), \
          "+f"(I)                                             \
        : "f"(a[0]), "f"(a[1]), "f"(a[2]), "f"(a[3]),         \
          "f"(a[4]), "f"(a[5]), "f"(a[6]), "f"(a[7]))

// ---------------- Kernel A: lean serial integrate chain ----------------
// 1 block, 512 threads. 16 warps: f64-sum (2 batches/warp) -> scales; stage
// scaled alphas transposed into double-buffered smem chunks (15 warps stage
// chunk c+1 while warp 0, lane = batch, runs the fused-asm serial chain).
__global__ void __launch_bounds__(512, 1) cif_scan_kernel(
    const float* __restrict__ alphas, const int* __restrict__ tlen)
{
    extern __shared__ float sa[];          // [2][CH*PAD], sa[buf][t*PAD + b]
    __shared__ float sscale[BB];

    const int tid = threadIdx.x;
    const int wid = tid >> 5;
    const int lid = tid & 31;

    // 1. per-warp f64 sums -> scale (f32 div as reference); 2 batches per warp
    for (int b = wid; b < BB; b += 16) {
        const float* arow = alphas + b * TT;
        double acc = 0.0;
        for (int t = lid; t < TT; t += 32) acc += (double)arow[t];
        #pragma unroll
        for (int o = 16; o; o >>= 1) acc += __shfl_down_sync(0xFFFFFFFFu, acc, o);
        if (lid == 0) {
            float s = (float)tlen[b] / (float)acc;
            sscale[b] = s;
            g_scale[b] = s;
        }
    }
    __syncthreads();

    // 2. stage chunk 0 (16 warps, 2 batches each), scaled + transposed
    for (int b = wid; b < BB; b += 16) {
        const float s = sscale[b];
        const float* src = alphas + b * TT;
        for (int t = lid; t < CH; t += 32)
            sa[t * PAD + b] = __fmul_rn(src[t], s);
    }
    __syncthreads();

    // 3. pipelined serial chain (warp 0) + next-chunk staging (warps 1..15)
    float I = 0.0f;
    for (int c = 0; c < NCH; ++c) {
        const int len = (TT - c * CH < CH) ? (TT - c * CH) : CH;
        if (wid > 0) {
            if (c + 1 < NCH) {
                const int base = (c + 1) * CH;
                const int len2 = (TT - base < CH) ? (TT - base) : CH;
                float* dst = sa + ((c + 1) & 1) * (CH * PAD);
                for (int b = wid - 1; b < BB; b += 15) {
                    const float s = sscale[b];
                    const float* src = alphas + b * TT + base;
                    for (int t = lid; t < len2; t += 32)
                        dst[t * PAD + b] = __fmul_rn(src[t], s);
                }
            }
        } else {
            const float* buf = sa + (c & 1) * (CH * PAD) + lid;
            const int tg = c * CH;
            for (int tt = 0; tt < len; tt += 8) {
                float av[8], Ib[8];
                #pragma unroll
                for (int j = 0; j < 8; ++j)          // plain LDS: ptxas schedules
                    av[j] = buf[(tt + j) * PAD];

                CIF_STEP8(I, av, Ib);                // fused 8-step chain

                float* Ip = g_I + lid * TT + tg + tt;
                *(float4*)(Ip)     = make_float4(Ib[0], Ib[1], Ib[2], Ib[3]);
                *(float4*)(Ip + 4) = make_float4(Ib[4], Ib[5], Ib[6], Ib[7]);
            }
        }
        __syncthreads();
    }
}

// ---------------- Kernel B: parallel bookkeeping ----------------
// Block = batch. Recompute fire/w/remainds bit-exactly from g_I + alphas*scale,
// block prefix-scan fires -> token indices, scatter fpos/carry, write w.
__global__ void __launch_bounds__(1024) cif_book_kernel(
    const float* __restrict__ alphas)
{
    __shared__ int wsum[32];
    __shared__ int stotal;

    const int b    = blockIdx.x;
    const int tid  = threadIdx.x;
    const int lane = tid & 31;
    const int wid  = tid >> 5;
    const float s  = g_scale[b];

    int f0 = 0, f1 = 0;
    float r0 = 0.f, r1 = 0.f;
    const int t0 = tid * 2;

    if (t0 < TT) {
        float a0 = __fmul_rn(alphas[b * TT + t0],     s);
        float a1 = __fmul_rn(alphas[b * TT + t0 + 1], s);
        float2 Iv = *(const float2*)&g_I[b * TT + t0];
        f0 = (__fadd_rn(Iv.x, a0) >= 0.95f);
        f1 = (__fadd_rn(Iv.y, a1) >= 0.95f);
        float w0 = f0 ? __fadd_rn(1.0f, -Iv.x) : a0;  // cur (reference ops)
        float w1 = f1 ? __fadd_rn(1.0f, -Iv.y) : a1;
        r0 = __fadd_rn(a0, -w0);                       // remainds
        r1 = __fadd_rn(a1, -w1);
        *(float2*)&g_w[b * TT + t0] = make_float2(w0, w1);
    }

    // block exclusive scan over fire counts
    int cnt = f0 + f1, sc = cnt;
    #pragma unroll
    for (int o = 1; o < 32; o <<= 1) {
        int v = __shfl_up_sync(0xFFFFFFFFu, sc, o);
        if (lane >= o) sc += v;
    }
    if (lane == 31) wsum[wid] = sc;
    __syncthreads();
    if (tid < 32) {
        int v = wsum[tid], s2 = v;
        #pragma unroll
        for (int o = 1; o < 32; o <<= 1) {
            int u = __shfl_up_sync(0xFFFFFFFFu, s2, o);
            if (tid >= o) s2 += u;
        }
        wsum[tid] = s2 - v;              // exclusive warp offsets
        if (tid == 31) stotal = s2;
    }
    __syncthreads();

    const int base = wsum[wid] + sc - cnt;
    if (f0 && base < LL) {
        g_fpos [b * LL1 + base]     = t0;
        g_carry[b * LL1 + base + 1] = r0;
    }
    const int k1 = base + f0;
    if (f1 && k1 < LL) {
        g_fpos [b * LL1 + k1]     = t0 + 1;
        g_carry[b * LL1 + k1 + 1] = r1;
    }
    if (tid == 0) {
        g_carry[b * LL1] = 0.0f;
        g_nf[b] = (stotal < LL) ? stotal : LL;
    }
}

// ---------------- Kernel C: weighted segmented reduction ----------------
__global__ void __launch_bounds__(128) cif_gather_kernel(
    const float* __restrict__ hidden, float* __restrict__ out)
{
    const int k  = blockIdx.x;
    const int b  = blockIdx.y;
    const int h4 = threadIdx.x;

    float4* o = (float4*)out + (size_t)(b * LL + k) * H4 + h4;

    const int nfb = g_nf[b];
    if (k >= nfb) {
        *o = make_float4(0.f, 0.f, 0.f, 0.f);
        return;
    }

    const float4* hid = (const float4*)hidden + (size_t)b * TT * H4 + h4;
    const float*  wrow = g_w + b * TT;

    const int e = g_fpos[b * LL1 + k];
    float4 acc = make_float4(0.f, 0.f, 0.f, 0.f);
    int t0;
    if (k == 0) {
        t0 = 0;
    } else {
        int   sfr = g_fpos[b * LL1 + k - 1];
        float cw  = g_carry[b * LL1 + k];
        float4 hv = hid[(size_t)sfr * H4];
        acc.x = cw * hv.x; acc.y = cw * hv.y;
        acc.z = cw * hv.z; acc.w = cw * hv.w;
        t0 = sfr + 1;
    }

    #pragma unroll 8
    for (int t = t0; t <= e; ++t) {
        float  w  = __ldg(wrow + t);
        float4 hv = hid[(size_t)t * H4];
        acc.x = fmaf(w, hv.x, acc.x);
        acc.y = fmaf(w, hv.y, acc.y);
        acc.z = fmaf(w, hv.z, acc.z);
        acc.w = fmaf(w, hv.w, acc.w);
    }
    *o = acc;
}

extern "C" void kernel_launch(void* const* d_in, const int* in_sizes, int n_in,
                              void* d_out, int out_size)
{
    const float* hidden = (const float*)d_in[0];   // [32,2000,512] f32
    const float* alphas = (const float*)d_in[1];   // [32,2000]     f32
    const int*   tlen   = (const int*)d_in[2];     // [32]          i32
    float*       out    = (float*)d_out;           // [32,256,512]  f32

    cudaFuncSetAttribute(cif_scan_kernel,
                         cudaFuncAttributeMaxDynamicSharedMemorySize, SMEMSZ);
    cif_scan_kernel<<<1, 512, SMEMSZ>>>(alphas, tlen);
    cif_book_kernel<<<BB, 1024>>>(alphas);
    dim3 grid(LL, BB);
    cif_gather_kernel<<<grid, 128>>>(hidden, out);
}

// round 17
// speedup vs baseline: 1.2436x; 1.1238x over previous
#include <cuda_runtime.h>
#include <cuda_bf16.h>
#include <cstdint>

#define BB 32
#define TT 2000
#define HH 512
#define LL 256
#define LL1 (LL+1)
#define H4 (HH/4)
#define NG4 (TT/4)      // 500 float4-blocks
#define NGRP (TT/8)     // 250 groups of 8 frames

// Scratch (device globals — no allocation allowed)
__device__ float4 g_aT4[NG4*BB];   // scaled alphas, blocked-transposed [t/4][b]
__device__ float4 g_IT4[NG4*BB];   // integrate state I, same layout
__device__ float  g_scale[BB];     // per-batch rescale factor
__device__ float  g_w[BB*TT];      // per-frame weight, row-major [b][t]
__device__ int    g_fpos[BB*LL1];  // frame index of k-th fire
__device__ float  g_carry[BB*LL1]; // carry weight into token k
__device__ int    g_nf[BB];        // emitted tokens (<= LL)

// 8 fused recurrence steps in ONE asm block (proven bit-exact in R16).
// Per step: Ib=I; t=I+a; f=(t>=0.95)?1.0:0.0 (FSET); I=t-f (Sterbenz-exact).
#define CIF_STEP8(I, a, Ib)                                   \
    asm("{\n\t"                                               \
        ".reg .f32 t, f;\n\t"                                 \
        "mov.f32 %0, %8;\n\t"                                 \
        "add.f32 t, %8, %9;\n\t"                              \
        "set.ge.f32.f32 f, t, 0f3F733333;\n\t"                \
        "sub.f32 %8, t, f;\n\t"                               \
        "mov.f32 %1, %8;\n\t"                                 \
        "add.f32 t, %8, %10;\n\t"                             \
        "set.ge.f32.f32 f, t, 0f3F733333;\n\t"                \
        "sub.f32 %8, t, f;\n\t"                               \
        "mov.f32 %2, %8;\n\t"                                 \
        "add.f32 t, %8, %11;\n\t"                             \
        "set.ge.f32.f32 f, t, 0f3F733333;\n\t"                \
        "sub.f32 %8, t, f;\n\t"                               \
        "mov.f32 %3, %8;\n\t"                                 \
        "add.f32 t, %8, %12;\n\t"                             \
        "set.ge.f32.f32 f, t, 0f3F733333;\n\t"                \
        "sub.f32 %8, t, f;\n\t"                               \
        "mov.f32 %4, %8;\n\t"                                 \
        "add.f32 t, %8, %13;\n\t"                             \
        "set.ge.f32.f32 f, t, 0f3F733333;\n\t"                \
        "sub.f32 %8, t, f;\n\t"                               \
        "mov.f32 %5, %8;\n\t"                                 \
        "add.f32 t, %8, %14;\n\t"                             \
        "set.ge.f32.f32 f, t, 0f3F733333;\n\t"                \
        "sub.f32 %8, t, f;\n\t"                               \
        "mov.f32 %6, %8;\n\t"                                 \
        "add.f32 t, %8, %15;\n\t"                             \
        "set.ge.f32.f32 f, t, 0f3F733333;\n\t"                \
        "sub.f32 %8, t, f;\n\t"                               \
        "mov.f32 %7, %8;\n\t"                                 \
        "add.f32 t, %8, %16;\n\t"                             \
        "set.ge.f32.f32 f, t, 0f3F733333;\n\t"                \
        "sub.f32 %8, t, f;\n\t"                               \
        "}"                                                   \
        : "=f"(Ib[0]), "=f"(Ib[1]), "=f"(Ib[2]), "=f"(Ib[3]), \
          "=f"(Ib[4]), "=f"(Ib[5]), "=f"(Ib[6]), "=f"(Ib[7]), \
          "+f"(I)                                             \
        : "f"(a[0]), "f"(a[1]), "f"(a[2]), "f"(a[3]),         \
          "f"(a[4]), "f"(a[5]), "f"(a[6]), "f"(a[7]))

// ---------------- Kernel A0: sums + scale + blocked-transposed staging ----
__global__ void __launch_bounds__(256) cif_prep_kernel(
    const float* __restrict__ alphas, const int* __restrict__ tlen)
{
    __shared__ double ssum[8];
    __shared__ float sscale;
    const int b = blockIdx.x, tid = threadIdx.x;
    const float* arow = alphas + b * TT;

    double acc = 0.0;
    for (int t = tid; t < TT; t += 256) acc += (double)arow[t];
    #pragma unroll
    for (int o = 16; o; o >>= 1) acc += __shfl_down_sync(0xFFFFFFFFu, acc, o);
    if ((tid & 31) == 0) ssum[tid >> 5] = acc;
    __syncthreads();
    if (tid == 0) {
        double s = 0.0;
        #pragma unroll
        for (int i = 0; i < 8; i++) s += ssum[i];
        float sc = (float)tlen[b] / (float)s;   // f32 div as reference
        sscale = sc;
        g_scale[b] = sc;
    }
    __syncthreads();
    const float sc = sscale;
    float* aT = (float*)g_aT4;
    for (int t = tid; t < TT; t += 256)
        aT[((t >> 2) * BB + b) * 4 + (t & 3)] = __fmul_rn(arow[t], sc);
}

// ---------------- Kernel A1: isolated serial chain (1 warp, nothing else) --
// Lane b runs batch b. Per 8-group: 2 coalesced LDG.128 (ring-4, distance-3
// prefetch), fused 8-step asm chain, 2 coalesced STG.128 of I.
__global__ void __launch_bounds__(32, 1) cif_chain_kernel()
{
    const int b = threadIdx.x;
    const float4* aT4 = g_aT4;
    float4* IT4 = g_IT4;

    float4 r0[4], r1[4];
    #pragma unroll
    for (int j = 0; j < 3; ++j) {                 // prologue: groups 0..2
        r0[j] = __ldg(&aT4[(2 * j)     * BB + b]);
        r1[j] = __ldg(&aT4[(2 * j + 1) * BB + b]);
    }

    float I = 0.0f;
    for (int gg = 0; gg < NGRP; gg += 4) {
        #pragma unroll
        for (int j = 0; j < 4; ++j) {
            const int g = gg + j;
            if (g < NGRP) {
                const int pg = g + 3;             // distance-3 prefetch
                if (pg < NGRP) {
                    r0[(j + 3) & 3] = __ldg(&aT4[(2 * pg)     * BB + b]);
                    r1[(j + 3) & 3] = __ldg(&aT4[(2 * pg + 1) * BB + b]);
                }
                float av[8] = { r0[j].x, r0[j].y, r0[j].z, r0[j].w,
                                r1[j].x, r1[j].y, r1[j].z, r1[j].w };
                float Ib[8];
                CIF_STEP8(I, av, Ib);

                IT4[(2 * g)     * BB + b] = make_float4(Ib[0], Ib[1], Ib[2], Ib[3]);
                IT4[(2 * g + 1) * BB + b] = make_float4(Ib[4], Ib[5], Ib[6], Ib[7]);
            }
        }
    }
}

// ---------------- Kernel B: parallel bookkeeping ----------------
__global__ void __launch_bounds__(1024) cif_book_kernel(
    const float* __restrict__ alphas)
{
    __shared__ int wsum[32];
    __shared__ int stotal;

    const int b    = blockIdx.x;
    const int tid  = threadIdx.x;
    const int lane = tid & 31;
    const int wid  = tid >> 5;
    const float s  = g_scale[b];
    const float* IT = (const float*)g_IT4;

    int f0 = 0, f1 = 0;
    float r0 = 0.f, r1 = 0.f;
    const int t0 = tid * 2;

    if (t0 < TT) {
        float a0 = __fmul_rn(alphas[b * TT + t0],     s);
        float a1 = __fmul_rn(alphas[b * TT + t0 + 1], s);
        const int idx = ((t0 >> 2) * BB + b) * 4 + (t0 & 3);  // 8B-aligned pair
        float2 Iv = *(const float2*)&IT[idx];
        f0 = (__fadd_rn(Iv.x, a0) >= 0.95f);
        f1 = (__fadd_rn(Iv.y, a1) >= 0.95f);
        float w0 = f0 ? __fadd_rn(1.0f, -Iv.x) : a0;  // cur (reference ops)
        float w1 = f1 ? __fadd_rn(1.0f, -Iv.y) : a1;
        r0 = __fadd_rn(a0, -w0);                       // remainds
        r1 = __fadd_rn(a1, -w1);
        *(float2*)&g_w[b * TT + t0] = make_float2(w0, w1);
    }

    int cnt = f0 + f1, sc = cnt;
    #pragma unroll
    for (int o = 1; o < 32; o <<= 1) {
        int v = __shfl_up_sync(0xFFFFFFFFu, sc, o);
        if (lane >= o) sc += v;
    }
    if (lane == 31) wsum[wid] = sc;
    __syncthreads();
    if (tid < 32) {
        int v = wsum[tid], s2 = v;
        #pragma unroll
        for (int o = 1; o < 32; o <<= 1) {
            int u = __shfl_up_sync(0xFFFFFFFFu, s2, o);
            if (tid >= o) s2 += u;
        }
        wsum[tid] = s2 - v;
        if (tid == 31) stotal = s2;
    }
    __syncthreads();

    const int base = wsum[wid] + sc - cnt;
    if (f0 && base < LL) {
        g_fpos [b * LL1 + base]     = t0;
        g_carry[b * LL1 + base + 1] = r0;
    }
    const int k1 = base + f0;
    if (f1 && k1 < LL) {
        g_fpos [b * LL1 + k1]     = t0 + 1;
        g_carry[b * LL1 + k1 + 1] = r1;
    }
    if (tid == 0) {
        g_carry[b * LL1] = 0.0f;
        g_nf[b] = (stotal < LL) ? stotal : LL;
    }
}

// ---------------- Kernel C: weighted segmented reduction ----------------
__global__ void __launch_bounds__(128) cif_gather_kernel(
    const float* __restrict__ hidden, float* __restrict__ out)
{
    const int k  = blockIdx.x;
    const int b  = blockIdx.y;
    const int h4 = threadIdx.x;

    float4* o = (float4*)out + (size_t)(b * LL + k) * H4 + h4;

    const int nfb = g_nf[b];
    if (k >= nfb) {
        *o = make_float4(0.f, 0.f, 0.f, 0.f);
        return;
    }

    const float4* hid = (const float4*)hidden + (size_t)b * TT * H4 + h4;
    const float*  wrow = g_w + b * TT;

    const int e = g_fpos[b * LL1 + k];
    float4 acc = make_float4(0.f, 0.f, 0.f, 0.f);
    int t0;
    if (k == 0) {
        t0 = 0;
    } else {
        int   sfr = g_fpos[b * LL1 + k - 1];
        float cw  = g_carry[b * LL1 + k];
        float4 hv = hid[(size_t)sfr * H4];
        acc.x = cw * hv.x; acc.y = cw * hv.y;
        acc.z = cw * hv.z; acc.w = cw * hv.w;
        t0 = sfr + 1;
    }

    #pragma unroll 8
    for (int t = t0; t <= e; ++t) {
        float  w  = __ldg(wrow + t);
        float4 hv = hid[(size_t)t * H4];
        acc.x = fmaf(w, hv.x, acc.x);
        acc.y = fmaf(w, hv.y, acc.y);
        acc.z = fmaf(w, hv.z, acc.z);
        acc.w = fmaf(w, hv.w, acc.w);
    }
    *o = acc;
}

extern "C" void kernel_launch(void* const* d_in, const int* in_sizes, int n_in,
                              void* d_out, int out_size)
{
    const float* hidden = (const float*)d_in[0];   // [32,2000,512] f32
    const float* alphas = (const float*)d_in[1];   // [32,2000]     f32
    const int*   tlen   = (const int*)d_in[2];     // [32]          i32
    float*       out    = (float*)d_out;           // [32,256,512]  f32

    cif_prep_kernel<<<BB, 256>>>(alphas, tlen);
    cif_chain_kernel<<<1, 32>>>();
    cif_book_kernel<<<BB, 1024>>>(alphas);
    dim3 grid(LL, BB);
    cif_gather_kernel<<<grid, 128>>>(hidden, out);
}